// round 10
// baseline (speedup 1.0000x reference)
#include <cuda_runtime.h>

#define TT 100
#define FF 3
#define BM 64
#define NTHR 256
#define MAXB 16384

typedef unsigned long long u64;

// ---------------- scratch (static __device__, zero-init, no allocations) ----------------
__device__ int g_len[MAXB];
__device__ int g_perm[MAXB];
__device__ int g_hist[101];   // zero at load; k_clear re-zeroes after each use
__device__ int g_cur[101];

// ---------------- helpers ----------------
__device__ __forceinline__ u64 pack2(float x, float y){
    u64 r; asm("mov.b64 %0, {%1, %2};" : "=l"(r) : "f"(x), "f"(y)); return r;
}
__device__ __forceinline__ void unpack2(u64 v, float &x, float &y){
    asm("mov.b64 {%0, %1}, %2;" : "=f"(x), "=f"(y) : "l"(v));
}
// packed f32x2 FMA: d = a*b + d
__device__ __forceinline__ void ffma2(u64 &d, u64 a, u64 b){
    asm("fma.rn.f32x2 %0, %1, %2, %0;" : "+l"(d) : "l"(a), "l"(b));
}
__device__ __forceinline__ float sigmoidf_(float x){
    return __fdividef(1.f, 1.f + __expf(-x));
}
__device__ __forceinline__ float tanhf_(float x){
    float ax = fabsf(x);
    float e  = __expf(-2.f * ax);
    float r  = __fdividef(1.f - e, 1.f + e);
    return copysignf(r, x);
}

// ---------------- prepass: lengths + counting sort (longest-first) ----------------
__global__ void k_len(const float* __restrict__ x, int B){
    int row = blockIdx.x * blockDim.x + threadIdx.x;
    if (row >= B) return;
    const float* p = x + (size_t)row * (TT * FF);
    int len = 0;
    for (int t = TT - 1; t >= 0; --t){
        float a = p[t*3], b = p[t*3+1], c = p[t*3+2];
        if (a != 0.f || b != 0.f || c != 0.f){ len = t + 1; break; }
    }
    g_len[row] = len;
    atomicAdd(&g_hist[len], 1);
}

__global__ void k_prefix(){
    if (threadIdx.x == 0 && blockIdx.x == 0){
        int run = 0;
        for (int l = 100; l >= 0; --l){ g_cur[l] = run; run += g_hist[l]; }
    }
}

__global__ void k_scatter(int B){
    int row = blockIdx.x * blockDim.x + threadIdx.x;
    if (row >= B) return;
    int p = atomicAdd(&g_cur[g_len[row]], 1);
    g_perm[p] = row;
}

__global__ void k_clear(){
    int i = threadIdx.x;
    if (i < 101) g_hist[i] = 0;
}

// ---------------- smem layout (bytes) ----------------
#define OFF_UA    0        // ulonglong2[64*32] = 32768   (gates 0,1 pairs (c, c+32))
#define OFF_UB    32768    // ulonglong2[64*32] = 32768   (gates 2,3)
#define OFF_HD    65536    // u64[64*64]        = 32768   (h duplicated pairs, [row][k])
#define OFF_WBP   98304    // ulonglong2[256]   = 4096    ((fd*2+gh)*32 + cg)
#define OFF_XS    102400   // float4[2][64]     = 2048
#define OFF_RID   104448   // int[64]
#define OFF_MISC  104704   // int[4]
#define SMEM_BYTES 104960
// head aliases the UA/UB region after the time loop:
#define OFF_W1S   0        // float[64*64] = 16384
#define OFF_H1S   16384    // float[64*65] = 16640 (padded rows)
#define OFF_B1S   33024    // float[64]
#define OFF_W2S   33280    // float[320]
#define OFF_B2S   34560    // float[8]

extern __shared__ char smem[];

__global__ void __launch_bounds__(NTHR, 1)
k_lstm(const float* __restrict__ x,
       const float* __restrict__ W,  const float* __restrict__ U,
       const float* __restrict__ b,
       const float* __restrict__ W1, const float* __restrict__ b1,
       const float* __restrict__ W2, const float* __restrict__ b2,
       float* __restrict__ out)
{
    ulonglong2* UA   = (ulonglong2*)(smem + OFF_UA);
    ulonglong2* UB   = (ulonglong2*)(smem + OFF_UB);
    u64*        HD   = (u64*)(smem + OFF_HD);
    ulonglong2* WBP  = (ulonglong2*)(smem + OFF_WBP);
    float4*     XSb  = (float4*)(smem + OFF_XS);     // [2][64]
    int*        RID  = (int*)(smem + OFF_RID);
    int*        MISC = (int*)(smem + OFF_MISC);

    const int tid = threadIdx.x;
    const int cg  = tid & 31;       // unit-pair (cg, cg+32)
    const int rg  = tid >> 5;       // warp id -> rows rg*8 .. rg*8+7
    const int r0  = rg * 8;

    // ---- stage U (lane-contiguous pair layout), W/b pairs; zero h ----
    for (int i = tid; i < 64*32; i += NTHR){
        const int c = i & 31, k = i >> 5;
        const float* Uk = U + k*256;
        ulonglong2 a, bb;
        a.x  = pack2(Uk[c],       Uk[c + 32]);        // gate 0
        a.y  = pack2(Uk[64 + c],  Uk[96 + c]);        // gate 1
        bb.x = pack2(Uk[128 + c], Uk[160 + c]);       // gate 2
        bb.y = pack2(Uk[192 + c], Uk[224 + c]);       // gate 3
        UA[i] = a; UB[i] = bb;
    }
    for (int i = tid; i < 256; i += NTHR){
        const int c = i & 31, gh = (i >> 5) & 1, fd = i >> 6;
        const float* src = (fd == 0) ? b : (W + (fd - 1) * 256);
        const int g0 = gh * 2, g1 = gh * 2 + 1;
        ulonglong2 v;
        v.x = pack2(src[g0*64 + c], src[g0*64 + 32 + c]);
        v.y = pack2(src[g1*64 + c], src[g1*64 + 32 + c]);
        WBP[i] = v;
    }
    for (int i = tid; i < 64*64; i += NTHR) HD[i] = 0ull;
    if (tid == 0) MISC[0] = 0;

    int myrow = 0;
    if (tid < BM){ myrow = g_perm[blockIdx.x * BM + tid]; RID[tid] = myrow; }
    __syncthreads();
    if (tid < BM) atomicMax(&MISC[0], g_len[myrow]);
    __syncthreads();
    const int maxlen = MISC[0];

    float c0[8], c1[8];
    #pragma unroll
    for (int i = 0; i < 8; ++i){ c0[i] = 0.f; c1[i] = 0.f; }

    const float* xptr = x + (size_t)((tid < BM) ? myrow : 0) * (TT * FF);

    // prefetch x for t=0
    float lx0 = 0.f, lx1 = 0.f, lx2 = 0.f;
    if (tid < BM){ lx0 = xptr[0]; lx1 = xptr[1]; lx2 = xptr[2]; }

    const u64 one2 = pack2(1.f, 1.f);

    for (int t = 0; t < maxlen; ++t){
        // publish x(t) into this step's buffer; prefetch x(t+1)
        if (tid < BM){
            const int m = (lx0 != 0.f) || (lx1 != 0.f) || (lx2 != 0.f);
            XSb[(t & 1) * 64 + tid] = make_float4(lx0, lx1, lx2, m ? 1.f : 0.f);
        }
        if (tid < BM && t + 1 < maxlen){
            lx0 = xptr[(t+1)*3]; lx1 = xptr[(t+1)*3+1]; lx2 = xptr[(t+1)*3+2];
        }

        // ---- z = h @ U  (packed f32x2; accumulators are (unit cg, unit cg+32)) ----
        u64 z[4][8];
        #pragma unroll
        for (int g = 0; g < 4; ++g)
            #pragma unroll
            for (int ri = 0; ri < 8; ++ri) z[g][ri] = 0ull;

        #pragma unroll 1
        for (int kb = 0; kb < 64; kb += 8){
            #pragma unroll
            for (int kp = 0; kp < 4; ++kp){
                const int k = kb + kp*2;
                const ulonglong2 ua = UA[k*32 + cg];         // gates 0,1 @ k
                const ulonglong2 ub = UB[k*32 + cg];         // gates 2,3 @ k
                const ulonglong2 uc = UA[(k+1)*32 + cg];     // gates 0,1 @ k+1
                const ulonglong2 ud = UB[(k+1)*32 + cg];     // gates 2,3 @ k+1
                #pragma unroll
                for (int ri = 0; ri < 8; ++ri){
                    const ulonglong2 hd = *(const ulonglong2*)&HD[(r0 + ri)*64 + k]; // (h_k,h_k),(h_{k+1},h_{k+1})
                    ffma2(z[0][ri], hd.x, ua.x);
                    ffma2(z[1][ri], hd.x, ua.y);
                    ffma2(z[2][ri], hd.x, ub.x);
                    ffma2(z[3][ri], hd.x, ub.y);
                    ffma2(z[0][ri], hd.y, uc.x);
                    ffma2(z[1][ri], hd.y, uc.y);
                    ffma2(z[2][ri], hd.y, ud.x);
                    ffma2(z[3][ri], hd.y, ud.y);
                }
            }
        }
        __syncthreads();   // HD reads done; XS[t&1] visible

        // per-thread W/b pairs (8 conflict-free LDS.128)
        u64 wb[4], w0[4], w1[4], w2[4];
        {
            ulonglong2 v;
            v = WBP[      cg]; wb[0] = v.x; wb[1] = v.y;
            v = WBP[ 32 + cg]; wb[2] = v.x; wb[3] = v.y;
            v = WBP[ 64 + cg]; w0[0] = v.x; w0[1] = v.y;
            v = WBP[ 96 + cg]; w0[2] = v.x; w0[3] = v.y;
            v = WBP[128 + cg]; w1[0] = v.x; w1[1] = v.y;
            v = WBP[160 + cg]; w1[2] = v.x; w1[3] = v.y;
            v = WBP[192 + cg]; w2[0] = v.x; w2[1] = v.y;
            v = WBP[224 + cg]; w2[2] = v.x; w2[3] = v.y;
        }

        // ---- gates + state update (mask uniform across warp) ----
        #pragma unroll
        for (int ri = 0; ri < 8; ++ri){
            const int r = r0 + ri;
            const float4 xv = XSb[(t & 1) * 64 + r];
            if (xv.w != 0.f){
                const u64 xd0 = pack2(xv.x, xv.x);
                const u64 xd1 = pack2(xv.y, xv.y);
                const u64 xd2 = pack2(xv.z, xv.z);
                float za[4], zb[4];
                #pragma unroll
                for (int g = 0; g < 4; ++g){
                    u64 zz = z[g][ri];
                    ffma2(zz, one2, wb[g]);
                    ffma2(zz, xd0, w0[g]);
                    ffma2(zz, xd1, w1[g]);
                    ffma2(zz, xd2, w2[g]);
                    unpack2(zz, za[g], zb[g]);
                }
                // unit cg
                {
                    const float ig = sigmoidf_(za[0]);
                    const float fg = sigmoidf_(za[1]);
                    const float gg = tanhf_(za[2]);
                    const float og = sigmoidf_(za[3]);
                    const float cn = fg * c0[ri] + ig * gg;
                    const float hn = og * tanhf_(cn);
                    c0[ri] = cn;
                    HD[r*64 + cg] = pack2(hn, hn);
                }
                // unit cg+32
                {
                    const float ig = sigmoidf_(zb[0]);
                    const float fg = sigmoidf_(zb[1]);
                    const float gg = tanhf_(zb[2]);
                    const float og = sigmoidf_(zb[3]);
                    const float cn = fg * c1[ri] + ig * gg;
                    const float hn = og * tanhf_(cn);
                    c1[ri] = cn;
                    HD[r*64 + cg + 32] = pack2(hn, hn);
                }
            }
        }
        __syncthreads();   // HD writes visible for next GEMM
    }

    // ---------------- head: relu(h@W1+b1) @ W2 + b2 -> softmax ----------------
    float* W1S = (float*)(smem + OFF_W1S);
    float* H1S = (float*)(smem + OFF_H1S);
    float* B1S = (float*)(smem + OFF_B1S);
    float* W2S = (float*)(smem + OFF_W2S);
    float* B2S = (float*)(smem + OFF_B2S);
    for (int i = tid; i < 4096; i += NTHR) W1S[i] = W1[i];
    for (int i = tid; i < 64;   i += NTHR) B1S[i] = b1[i];
    for (int i = tid; i < 320;  i += NTHR) W2S[i] = W2[i];
    for (int i = tid; i < 5;    i += NTHR) B2S[i] = b2[i];
    __syncthreads();

    {   // h1: 4 threads per row, 16 outputs each
        const int r = tid >> 2, part = tid & 3;
        float acc[16];
        #pragma unroll
        for (int j = 0; j < 16; ++j) acc[j] = 0.f;
        for (int k = 0; k < 64; ++k){
            const float hk = *(const float*)&HD[r*64 + k];   // low lane of (h,h)
            const float* wr = W1S + k*64 + part*16;
            #pragma unroll
            for (int j = 0; j < 16; ++j) acc[j] += hk * wr[j];
        }
        #pragma unroll
        for (int j = 0; j < 16; ++j){
            float v = acc[j] + B1S[part*16 + j];
            H1S[r*65 + part*16 + j] = v > 0.f ? v : 0.f;
        }
    }
    __syncthreads();

    if (tid < BM){
        float lg[5];
        #pragma unroll
        for (int q = 0; q < 5; ++q) lg[q] = B2S[q];
        for (int k = 0; k < 64; ++k){
            const float v = H1S[tid*65 + k];
            #pragma unroll
            for (int q = 0; q < 5; ++q) lg[q] += v * W2S[k*5 + q];
        }
        float mx = lg[0];
        #pragma unroll
        for (int q = 1; q < 5; ++q) mx = fmaxf(mx, lg[q]);
        float e[5], s = 0.f;
        #pragma unroll
        for (int q = 0; q < 5; ++q){ e[q] = __expf(lg[q] - mx); s += e[q]; }
        const float inv = __fdividef(1.f, s);
        const int grow = RID[tid];
        #pragma unroll
        for (int q = 0; q < 5; ++q) out[grow*5 + q] = e[q] * inv;
    }
}

// ---------------- launch ----------------
extern "C" void kernel_launch(void* const* d_in, const int* in_sizes, int n_in,
                              void* d_out, int out_size)
{
    const float *x=0, *W=0, *U=0, *b=0, *W1=0, *b1=0, *W2=0, *b2=0;
    int xsize = 0;
    for (int i = 0; i < n_in; ++i){
        const float* p = (const float*)d_in[i];
        switch (in_sizes[i]){
            case 768:    W  = p; break;
            case 16384:  U  = p; break;
            case 256:    b  = p; break;
            case 4096:   W1 = p; break;
            case 64:     b1 = p; break;
            case 320:    W2 = p; break;
            case 5:      b2 = p; break;
            default:     x  = p; xsize = in_sizes[i]; break;
        }
    }
    float* out = (float*)d_out;
    const int B = xsize / (TT * FF);   // 16384

    cudaFuncSetAttribute(k_lstm, cudaFuncAttributeMaxDynamicSharedMemorySize, SMEM_BYTES);

    // launch order keeps k_lstm at index 3 (ncu's capture slot last round)
    k_len<<<(B + 255) / 256, 256>>>(x, B);         // idx 0 (g_hist is zero: static init / k_clear)
    k_prefix<<<1, 32>>>();                         // idx 1
    k_scatter<<<(B + 255) / 256, 256>>>(B);        // idx 2
    k_lstm<<<B / BM, NTHR, SMEM_BYTES>>>(x, W, U, b, W1, b1, W2, b2, out);  // idx 3
    k_clear<<<1, 128>>>();                         // idx 4: re-zero g_hist for next call
}